// round 1
// baseline (speedup 1.0000x reference)
#include <cuda_runtime.h>
#include <cuda_bf16.h>
#include <cstdint>

// ---------------------------------------------------------------------------
// Problem constants (fixed shapes)
// ---------------------------------------------------------------------------
#define N_R       2000
#define N_P       1512
#define M_TOT     3512          // N_R + N_P
#define SIZE_R    3000
#define FUN_IN    5603
#define ATT_H     2048
#define FUN_H     4096
#define ATT       256
#define FUN       256
#define DFEAT     512           // ATT + FUN
#define BATCH     8192

// output layout offsets (floats)
#define EP_OFF    (N_R * DFEAT)                 // 1,024,000
#define OUT2_OFF  (EP_OFF + N_P * DFEAT)        // 1,798,144
#define FLAT_OFF  (OUT2_OFF + BATCH * 2)        // 1,814,528

// scratch: reused for H_att (3512x2048) then H_fun (3512x4096)
__device__ float g_H[(size_t)M_TOT * FUN_H];

__device__ __forceinline__ float gelu_f(float x) {
    return 0.5f * x * (1.0f + erff(x * 0.70710678118654752f));
}
__device__ __forceinline__ float sigmoid_f(float x) {
    return 1.0f / (1.0f + expf(-x));
}

// ---------------------------------------------------------------------------
// Tiled fp32 GEMM:  C(M,N) = act( A(M,K) @ B(K,N) + bias )
// A rows come from A0 (row < splitRow) else A1 (row - splitRow)  (concat).
// EPI 0: gelu -> C[row*ldc + col]
// EPI 1: sigmoid -> scatter into d_out e_r / e_p regions at column colOff+col
// ---------------------------------------------------------------------------
template <int BM, int BN, int BK, int TM, int TN, int EPI>
__global__ __launch_bounds__(256)
void gemm_k(const float* __restrict__ A0, const float* __restrict__ A1, int splitRow,
            int M, int N, int K, int lda,
            const float* __restrict__ B, const float* __restrict__ bias,
            float* __restrict__ C, int ldc, int colOff)
{
    static_assert((BM / TM) * (BN / TN) == 256, "256 threads");
    __shared__ float As[BK][BM];
    __shared__ float Bs[BK][BN];

    const int tid = threadIdx.x;
    const int tx  = tid % (BN / TN);
    const int ty  = tid / (BN / TN);
    const int bm0 = blockIdx.y * BM;
    const int bn0 = blockIdx.x * BN;

    float acc[TM][TN];
#pragma unroll
    for (int i = 0; i < TM; ++i)
#pragma unroll
        for (int j = 0; j < TN; ++j) acc[i][j] = 0.0f;

    constexpr int ALOAD = (BM * BK) / 256;
    constexpr int BLOAD = (BK * BN) / 256;

    for (int kt = 0; kt < K; kt += BK) {
#pragma unroll
        for (int r = 0; r < ALOAD; ++r) {
            int i = tid + r * 256;
            int m = i % BM, k = i / BM;
            int gm = bm0 + m, gk = kt + k;
            float v = 0.0f;
            if (gm < M && gk < K) {
                const float* Ar = (gm < splitRow)
                                      ? (A0 + (size_t)gm * lda)
                                      : (A1 + (size_t)(gm - splitRow) * lda);
                v = Ar[gk];
            }
            As[k][m] = v;
        }
#pragma unroll
        for (int r = 0; r < BLOAD; ++r) {
            int i = tid + r * 256;
            int n = i % BN, k = i / BN;
            int gk = kt + k;
            Bs[k][n] = (gk < K) ? B[(size_t)gk * N + (bn0 + n)] : 0.0f;
        }
        __syncthreads();

#pragma unroll
        for (int k = 0; k < BK; ++k) {
            float ra[TM], rb[TN];
#pragma unroll
            for (int i = 0; i < TM; ++i) ra[i] = As[k][ty * TM + i];
#pragma unroll
            for (int j = 0; j < TN; ++j) rb[j] = Bs[k][tx * TN + j];
#pragma unroll
            for (int i = 0; i < TM; ++i)
#pragma unroll
                for (int j = 0; j < TN; ++j)
                    acc[i][j] = fmaf(ra[i], rb[j], acc[i][j]);
        }
        __syncthreads();
    }

#pragma unroll
    for (int i = 0; i < TM; ++i) {
        int gm = bm0 + ty * TM + i;
        if (gm >= M) continue;
#pragma unroll
        for (int j = 0; j < TN; ++j) {
            int gn = bn0 + tx * TN + j;
            float v = acc[i][j] + bias[gn];
            if (EPI == 0) {
                C[(size_t)gm * ldc + gn] = gelu_f(v);
            } else {
                float s = sigmoid_f(v);
                float* dst = (gm < N_R)
                                 ? (C + (size_t)gm * DFEAT + colOff + gn)
                                 : (C + EP_OFF + (size_t)(gm - N_R) * DFEAT + colOff + gn);
                *dst = s;
            }
        }
    }
}

// ---------------------------------------------------------------------------
// CNN head: one block per sample (256 threads).
//  x(1,2,512) -> conv1(16,3x5,pad2) -> leaky -> avgpool2 -> (16,2,256)
//            -> conv2(32,3x5,pad2) -> leaky -> maxpool2 -> tanh -> flat(8192)
//            -> out(2) = flat @ W_out + b_out
// ---------------------------------------------------------------------------
// shared layout (floats):
//  s_x   [2*516]      padded (+2 each side) e rows
//  s_w1  [240] s_b1[16] s_b2[32]
//  s_w2  [7680]
//  s_p1  [16*2*260]   padded pooled conv1 output
//  s_red [16]
#define SMX    0
#define SMW1   (SMX  + 2 * 516)
#define SMB1   (SMW1 + 240)
#define SMB2   (SMB1 + 16)
#define SMW2   (SMB2 + 32)
#define SMP1   (SMW2 + 7680)
#define SMRED  (SMP1 + 16 * 2 * 260)
#define SMTOT  (SMRED + 16)               // 17336 floats = 69344 bytes

__global__ __launch_bounds__(256)
void conv_head_k(const float* __restrict__ w1, const float* __restrict__ b1,
                 const float* __restrict__ w2, const float* __restrict__ b2,
                 const int* __restrict__ idx,
                 const float* __restrict__ Wout, const float* __restrict__ bout,
                 float* __restrict__ out)
{
    extern __shared__ float sm[];
    float* s_x  = sm + SMX;
    float* s_w1 = sm + SMW1;
    float* s_b1 = sm + SMB1;
    float* s_b2 = sm + SMB2;
    float* s_w2 = sm + SMW2;
    float* s_p1 = sm + SMP1;
    float* s_red = sm + SMRED;

    const int tid = threadIdx.x;
    const int b   = blockIdx.x;

    // ---- zero padded planes + load weights ----
    for (int i = tid; i < 2 * 516; i += 256) s_x[i] = 0.0f;
    for (int i = tid; i < 16 * 2 * 260; i += 256) s_p1[i] = 0.0f;
    for (int i = tid; i < 240; i += 256) s_w1[i] = w1[i];
    for (int i = tid; i < 7680; i += 256) s_w2[i] = w2[i];
    if (tid < 16) s_b1[tid] = b1[tid];
    if (tid >= 32 && tid < 64) s_b2[tid - 32] = b2[tid - 32];

    const int id   = idx[b];
    const int r_no = id / 1512;
    const int p_no = id - r_no * 1512;
    __syncthreads();

    // ---- gather e rows from d_out ----
    for (int c = tid; c < DFEAT; c += 256) {
        s_x[2 + c]        = out[(size_t)r_no * DFEAT + c];
        s_x[516 + 2 + c]  = out[EP_OFF + (size_t)p_no * DFEAT + c];
    }
    __syncthreads();

    // ---- conv1 + leaky + avgpool -> s_p1 (16,2,256) ----
    for (int j = tid; j < 16 * 2 * 256; j += 256) {
        const int oc = j >> 9;
        const int ph = (j >> 8) & 1;
        const int pw = j & 255;
        const float* w = s_w1 + oc * 15;
        const float bv = s_b1[oc];
        float sum = 0.0f;
#pragma unroll
        for (int dh = 0; dh < 2; ++dh) {
            const int oh = 2 * ph + dh;
#pragma unroll
            for (int dw = 0; dw < 2; ++dw) {
                const int ow = 2 * pw + dw;
                float c = 0.0f;
#pragma unroll
                for (int kh = 0; kh < 3; ++kh) {
                    const int ih = oh + kh - 2;
                    if (ih >= 0 && ih < 2) {
#pragma unroll
                        for (int kw = 0; kw < 5; ++kw)
                            c = fmaf(w[kh * 5 + kw], s_x[ih * 516 + ow + kw], c);
                    }
                }
                c += bv;
                sum += (c >= 0.0f) ? c : 0.01f * c;
            }
        }
        s_p1[(oc * 2 + ph) * 260 + 2 + pw] = 0.25f * sum;
    }
    __syncthreads();

    // ---- conv2 + leaky + maxpool + tanh + flat + partial out-GEMM ----
    // 1024 tasks: task t -> ocg = t>>7 (4 oc each), ph = (t>>6)&1, pwg = t&63
    // thread tile: 4 oc x 4 conv-ow (= 2 pooled outputs), both oh rows.
    float ro0 = 0.0f, ro1 = 0.0f;
#pragma unroll
    for (int pass = 0; pass < 4; ++pass) {
        const int t   = tid + pass * 256;
        const int ocg = t >> 7;          // 0..7  (warp-uniform)
        const int ph  = (t >> 6) & 1;    // warp-uniform
        const int pwg = t & 63;          // lane-contiguous
        const int ow0 = pwg * 4;         // 16B-aligned smem base

        float accA[4][4], accB[4][4];
#pragma unroll
        for (int o = 0; o < 4; ++o)
#pragma unroll
            for (int j = 0; j < 4; ++j) { accA[o][j] = 0.0f; accB[o][j] = 0.0f; }

        const int khA0 = 2 - 2 * ph;     // khA = ih + khA0 ; khB = khA - 1
#pragma unroll
        for (int ic = 0; ic < 16; ++ic) {
#pragma unroll
            for (int ih = 0; ih < 2; ++ih) {
                const float* rowp = s_p1 + (ic * 2 + ih) * 260;
                float4 u0 = *reinterpret_cast<const float4*>(rowp + ow0);
                float4 u1 = *reinterpret_cast<const float4*>(rowp + ow0 + 4);
                float in[8] = {u0.x, u0.y, u0.z, u0.w, u1.x, u1.y, u1.z, u1.w};

                const int khA = ih + khA0;
                if (khA >= 0 && khA < 3) {
#pragma unroll
                    for (int o = 0; o < 4; ++o) {
                        const float* w = s_w2 + ((((ocg * 4 + o) * 16 + ic) * 3 + khA) * 5);
#pragma unroll
                        for (int kw = 0; kw < 5; ++kw) {
                            const float wv = w[kw];
#pragma unroll
                            for (int j = 0; j < 4; ++j)
                                accA[o][j] = fmaf(wv, in[j + kw], accA[o][j]);
                        }
                    }
                }
                const int khB = khA - 1;
                if (khB >= 0 && khB < 3) {
#pragma unroll
                    for (int o = 0; o < 4; ++o) {
                        const float* w = s_w2 + ((((ocg * 4 + o) * 16 + ic) * 3 + khB) * 5);
#pragma unroll
                        for (int kw = 0; kw < 5; ++kw) {
                            const float wv = w[kw];
#pragma unroll
                            for (int j = 0; j < 4; ++j)
                                accB[o][j] = fmaf(wv, in[j + kw], accB[o][j]);
                        }
                    }
                }
            }
        }
        // pool (max over 2x2), leaky (monotone: after max), tanh, emit
#pragma unroll
        for (int o = 0; o < 4; ++o) {
            const int oc = ocg * 4 + o;
            const float bv = s_b2[oc];
#pragma unroll
            for (int p = 0; p < 2; ++p) {
                float m = fmaxf(fmaxf(accA[o][2 * p], accA[o][2 * p + 1]),
                                fmaxf(accB[o][2 * p], accB[o][2 * p + 1]));
                float v = m + bv;
                v = (v >= 0.0f) ? v : 0.01f * v;
                float tv = tanhf(v);
                const int f = oc * 256 + ph * 128 + (pwg * 2 + p);
                out[FLAT_OFF + (size_t)b * 8192 + f] = tv;
                ro0 = fmaf(tv, Wout[2 * f], ro0);
                ro1 = fmaf(tv, Wout[2 * f + 1], ro1);
            }
        }
    }

    // ---- block reduce -> output[b] ----
#pragma unroll
    for (int off = 16; off > 0; off >>= 1) {
        ro0 += __shfl_down_sync(0xffffffffu, ro0, off);
        ro1 += __shfl_down_sync(0xffffffffu, ro1, off);
    }
    const int warp = tid >> 5, lane = tid & 31;
    if (lane == 0) { s_red[warp] = ro0; s_red[8 + warp] = ro1; }
    __syncthreads();
    if (tid == 0) {
        float a = 0.0f, c = 0.0f;
#pragma unroll
        for (int i = 0; i < 8; ++i) { a += s_red[i]; c += s_red[8 + i]; }
        out[OUT2_OFF + (size_t)b * 2 + 0] = a + bout[0];
        out[OUT2_OFF + (size_t)b * 2 + 1] = c + bout[1];
    }
}

// ---------------------------------------------------------------------------
extern "C" void kernel_launch(void* const* d_in, const int* in_sizes, int n_in,
                              void* d_out, int out_size)
{
    const float* r_att   = (const float*)d_in[0];
    const float* p_att   = (const float*)d_in[1];
    const float* r_fun   = (const float*)d_in[2];
    const float* p_fun   = (const float*)d_in[3];
    const int*   idx     = (const int*)  d_in[4];
    const float* W_att1  = (const float*)d_in[5];
    const float* b_att1  = (const float*)d_in[6];
    const float* W_att2  = (const float*)d_in[7];
    const float* b_att2  = (const float*)d_in[8];
    const float* W_fun1  = (const float*)d_in[9];
    const float* b_fun1  = (const float*)d_in[10];
    const float* W_fun2  = (const float*)d_in[11];
    const float* b_fun2  = (const float*)d_in[12];
    const float* conv1_w = (const float*)d_in[13];
    const float* conv1_b = (const float*)d_in[14];
    const float* conv2_w = (const float*)d_in[15];
    const float* conv2_b = (const float*)d_in[16];
    const float* W_out   = (const float*)d_in[17];
    const float* b_out   = (const float*)d_in[18];
    float* out = (float*)d_out;

    float* Hbuf = nullptr;
    cudaGetSymbolAddress((void**)&Hbuf, g_H);

    const size_t conv_smem = SMTOT * sizeof(float);
    cudaFuncSetAttribute(conv_head_k, cudaFuncAttributeMaxDynamicSharedMemorySize,
                         (int)conv_smem);

    // 1) att hidden: gelu( [r_att;p_att] @ W_att1 + b ) -> g_H (3512 x 2048)
    {
        dim3 grid(ATT_H / 128, (M_TOT + 127) / 128);
        gemm_k<128, 128, 8, 8, 8, 0><<<grid, 256>>>(
            r_att, p_att, N_R, M_TOT, ATT_H, SIZE_R, SIZE_R,
            W_att1, b_att1, Hbuf, ATT_H, 0);
    }
    // 2) e_att: sigmoid( g_H @ W_att2 + b ) -> d_out e cols [0,256)
    {
        dim3 grid(ATT / 64, (M_TOT + 63) / 64);
        gemm_k<64, 64, 8, 4, 4, 1><<<grid, 256>>>(
            Hbuf, Hbuf, M_TOT, M_TOT, ATT, ATT_H, ATT_H,
            W_att2, b_att2, out, 0, 0);
    }
    // 3) fun hidden: gelu( [r_fun;p_fun] @ W_fun1 + b ) -> g_H (3512 x 4096)
    {
        dim3 grid(FUN_H / 128, (M_TOT + 127) / 128);
        gemm_k<128, 128, 8, 8, 8, 0><<<grid, 256>>>(
            r_fun, p_fun, N_R, M_TOT, FUN_H, FUN_IN, FUN_IN,
            W_fun1, b_fun1, Hbuf, FUN_H, 0);
    }
    // 4) e_fun: sigmoid( g_H @ W_fun2 + b ) -> d_out e cols [256,512)
    {
        dim3 grid(FUN / 64, (M_TOT + 63) / 64);
        gemm_k<64, 64, 8, 4, 4, 1><<<grid, 256>>>(
            Hbuf, Hbuf, M_TOT, M_TOT, FUN, FUN_H, FUN_H,
            W_fun2, b_fun2, out, 0, 256);
    }
    // 5) CNN head: one block per sample
    conv_head_k<<<BATCH, 256, conv_smem>>>(
        conv1_w, conv1_b, conv2_w, conv2_b, idx, W_out, b_out, out);

    (void)in_sizes; (void)n_in; (void)out_size;
}

// round 7
// speedup vs baseline: 1.2286x; 1.2286x over previous
#include <cuda_runtime.h>
#include <cuda_bf16.h>
#include <cstdint>

// ---------------------------------------------------------------------------
// Problem constants
// ---------------------------------------------------------------------------
#define N_R       2000
#define N_P       1512
#define M_TOT     3512
#define SIZE_R    3000
#define FUN_IN    5603
#define ATT_H     2048
#define FUN_H     4096
#define DFEAT     512
#define BATCH     8192
#define KP_ATT    3008          // SIZE_R padded to 32
#define KP_FUN    5632          // FUN_IN padded to 32

#define EP_OFF    (N_R * DFEAT)
#define OUT2_OFF  (EP_OFF + N_P * DFEAT)
#define FLAT_OFF  (OUT2_OFF + BATCH * 2)

// ---------------------------------------------------------------------------
// Scratch (bf16 stored as ushort), 16B-aligned
// ---------------------------------------------------------------------------
__device__ __align__(256) unsigned short gAh[(size_t)M_TOT * KP_FUN];
__device__ __align__(256) unsigned short gAl[(size_t)M_TOT * KP_FUN];
__device__ __align__(256) unsigned short gBh[(size_t)KP_FUN * FUN_H];
__device__ __align__(256) unsigned short gBl[(size_t)KP_FUN * FUN_H];
__device__ __align__(256) unsigned short gHh[(size_t)M_TOT * FUN_H];
__device__ __align__(256) unsigned short gHl[(size_t)M_TOT * FUN_H];

// ---------------------------------------------------------------------------
// Base-ISA async-copy / ldmatrix / mma helpers (all sm_80+ base features)
// ---------------------------------------------------------------------------
__device__ __forceinline__ uint32_t smem_to_u32(const void* p) {
    uint32_t a;
    asm("{ .reg .u64 t; cvta.to.shared.u64 t, %1; cvt.u32.u64 %0, t; }" : "=r"(a) : "l"(p));
    return a;
}
__device__ __forceinline__ void cp_async16(uint32_t dst, const void* src) {
    asm volatile("cp.async.cg.shared.global [%0], [%1], 16;\n" :: "r"(dst), "l"(src));
}
__device__ __forceinline__ void cp_commit() {
    asm volatile("cp.async.commit_group;\n" ::: "memory");
}
__device__ __forceinline__ void cp_wait1() {
    asm volatile("cp.async.wait_group 1;\n" ::: "memory");
}
__device__ __forceinline__ void cp_wait0() {
    asm volatile("cp.async.wait_group 0;\n" ::: "memory");
}
__device__ __forceinline__ void ldm_x4(uint32_t& r0, uint32_t& r1, uint32_t& r2, uint32_t& r3,
                                       uint32_t addr) {
    asm volatile("ldmatrix.sync.aligned.m8n8.x4.shared.b16 {%0,%1,%2,%3}, [%4];"
                 : "=r"(r0), "=r"(r1), "=r"(r2), "=r"(r3) : "r"(addr));
}
__device__ __forceinline__ void mma_bf16(float* c, const uint32_t* a, const uint32_t* b) {
    asm volatile("mma.sync.aligned.m16n8k16.row.col.f32.bf16.bf16.f32 "
                 "{%0,%1,%2,%3}, {%4,%5,%6,%7}, {%8,%9}, {%0,%1,%2,%3};"
                 : "+f"(c[0]), "+f"(c[1]), "+f"(c[2]), "+f"(c[3])
                 : "r"(a[0]), "r"(a[1]), "r"(a[2]), "r"(a[3]), "r"(b[0]), "r"(b[1]));
}

// ---------------------------------------------------------------------------
// Split conversions (f32 -> bf16 hi/lo)
// ---------------------------------------------------------------------------
__device__ __forceinline__ void split2(float x, unsigned short* H, unsigned short* L, size_t o) {
    __nv_bfloat16 h = __float2bfloat16(x);
    __nv_bfloat16 l = __float2bfloat16(x - __bfloat162float(h));
    ((__nv_bfloat16*)H)[o] = h;
    ((__nv_bfloat16*)L)[o] = l;
}

__global__ void convA_split(const float* __restrict__ A0, const float* __restrict__ A1,
                            int split, int K, int Kpad,
                            unsigned short* __restrict__ Ah, unsigned short* __restrict__ Al)
{
    const int k = blockIdx.x * 256 + threadIdx.x;
    const int m = blockIdx.y;
    if (k >= Kpad) return;
    float x = 0.0f;
    if (k < K)
        x = (m < split) ? A0[(size_t)m * K + k] : A1[(size_t)(m - split) * K + k];
    split2(x, Ah, Al, (size_t)m * Kpad + k);
}

__global__ void convT_split(const float* __restrict__ W, int K, int N, int Kpad,
                            unsigned short* __restrict__ Bh, unsigned short* __restrict__ Bl)
{
    __shared__ float t[32][33];
    const int n0 = blockIdx.x * 32, k0 = blockIdx.y * 32;
    for (int r = threadIdx.y; r < 32; r += 8) {
        int k = k0 + r;
        t[r][threadIdx.x] = (k < K) ? W[(size_t)k * N + n0 + threadIdx.x] : 0.0f;
    }
    __syncthreads();
    for (int r = threadIdx.y; r < 32; r += 8) {
        int n = n0 + r, k = k0 + threadIdx.x;
        split2(t[threadIdx.x][r], Bh, Bl, (size_t)n * Kpad + k);
    }
}

// ---------------------------------------------------------------------------
// HMMA (mma.sync) split-bf16 GEMM:  C(M,N) = act( A @ B^T + bias )
//   A:(M,Kpad) bf16 hi/lo (row clamped, garbage rows discarded)
//   B:(N,Kpad) bf16 hi/lo.  Block 128x128, BK=32, 8 warps (warp tile 64x32).
// EPI 0: gelu -> bf16 hi/lo to Hh/Hl (ld = N)
// EPI 1: sigmoid -> scatter to d_out e_r/e_p at column colOff+gn
// ---------------------------------------------------------------------------
#define ROWSTRIDE 40                       // elements per smem row (80B, conflict-free)
#define TILE_B    (128 * ROWSTRIDE * 2)    // 10240 bytes per tile
#define OFF_AH    0
#define OFF_AL    (TILE_B)
#define OFF_BH    (2 * TILE_B)
#define OFF_BL    (3 * TILE_B)
#define BUF_B     (4 * TILE_B)             // 40960 bytes per buffer
#define HS_SMEM   (2 * BUF_B)              // 81920 bytes

__device__ __forceinline__ void load_chunk(uint32_t smb, uint32_t bufoff,
                                           const unsigned short* __restrict__ Ah,
                                           const unsigned short* __restrict__ Al,
                                           const unsigned short* __restrict__ Bh,
                                           const unsigned short* __restrict__ Bl,
                                           int bm0, int bn0, int M, int Kpad, int kt, int tid)
{
#pragma unroll
    for (int r = 0; r < 2; ++r) {
        const int i   = tid + r * 256;
        const int row = i >> 2;
        const int ch  = i & 3;
        const uint32_t soff = (uint32_t)(row * (ROWSTRIDE * 2) + ch * 16);
        int gm = bm0 + row; if (gm >= M) gm = M - 1;          // clamp: rows >= M discarded
        const size_t ga = (size_t)gm * Kpad + kt + ch * 8;
        const size_t gb = (size_t)(bn0 + row) * Kpad + kt + ch * 8;
        cp_async16(smb + bufoff + OFF_AH + soff, Ah + ga);
        cp_async16(smb + bufoff + OFF_AL + soff, Al + ga);
        cp_async16(smb + bufoff + OFF_BH + soff, Bh + gb);
        cp_async16(smb + bufoff + OFF_BL + soff, Bl + gb);
    }
}

template <int EPI>
__global__ __launch_bounds__(256)
void hmma_gemm(const unsigned short* __restrict__ Ah, const unsigned short* __restrict__ Al,
               int M, int Kpad,
               const unsigned short* __restrict__ Bh, const unsigned short* __restrict__ Bl,
               int N, const float* __restrict__ bias,
               float* __restrict__ outp,
               unsigned short* __restrict__ Hh, unsigned short* __restrict__ Hl,
               int colOff)
{
    extern __shared__ char smraw[];
    const uint32_t smb = smem_to_u32(smraw);
    const int tid = threadIdx.x;
    const int l   = tid & 31;
    const int w   = tid >> 5;
    const int wr  = w >> 2;           // 0..1
    const int wc  = w & 3;            // 0..3
    const int bm0 = blockIdx.y * 128;
    const int bn0 = blockIdx.x * 128;

    // per-thread ldmatrix offset: row = l&15, k-half = l>>4 (8 elems)
    const uint32_t lm_off = (uint32_t)(((l & 15) * ROWSTRIDE + ((l >> 4) & 1) * 8) * 2);

    float acc[4][4][4];
#pragma unroll
    for (int mi = 0; mi < 4; ++mi)
#pragma unroll
        for (int ni = 0; ni < 4; ++ni)
#pragma unroll
            for (int r = 0; r < 4; ++r) acc[mi][ni][r] = 0.0f;

    const int nc = Kpad >> 5;
    load_chunk(smb, 0, Ah, Al, Bh, Bl, bm0, bn0, M, Kpad, 0, tid);
    cp_commit();

    for (int c = 0; c < nc; ++c) {
        if (c + 1 < nc) {
            load_chunk(smb, (uint32_t)(((c + 1) & 1) * BUF_B), Ah, Al, Bh, Bl,
                       bm0, bn0, M, Kpad, (c + 1) << 5, tid);
            cp_commit();
            cp_wait1();
        } else {
            cp_wait0();
        }
        __syncthreads();

        const uint32_t bo = smb + (uint32_t)((c & 1) * BUF_B);
#pragma unroll
        for (int ks = 0; ks < 2; ++ks) {
            const uint32_t kso = (uint32_t)(ks * 16 * 2);
            uint32_t af[2][4][4];
            uint32_t bf[2][4][2];
#pragma unroll
            for (int s = 0; s < 2; ++s) {
                const uint32_t abase = bo + (s ? OFF_AL : OFF_AH) + kso + lm_off;
#pragma unroll
                for (int mi = 0; mi < 4; ++mi)
                    ldm_x4(af[s][mi][0], af[s][mi][1], af[s][mi][2], af[s][mi][3],
                           abase + (uint32_t)((wr * 64 + mi * 16) * ROWSTRIDE * 2));
                const uint32_t bbase = bo + (s ? OFF_BL : OFF_BH) + kso + lm_off;
#pragma unroll
                for (int np = 0; np < 2; ++np) {
                    uint32_t q0, q1, q2, q3;
                    ldm_x4(q0, q1, q2, q3,
                           bbase + (uint32_t)((wc * 32 + np * 16) * ROWSTRIDE * 2));
                    bf[s][np * 2 + 0][0] = q0; bf[s][np * 2 + 0][1] = q2;
                    bf[s][np * 2 + 1][0] = q1; bf[s][np * 2 + 1][1] = q3;
                }
            }
#pragma unroll
            for (int mi = 0; mi < 4; ++mi)
#pragma unroll
                for (int ni = 0; ni < 4; ++ni) {
                    mma_bf16(acc[mi][ni], af[0][mi], bf[0][ni]);   // hi*hi
                    mma_bf16(acc[mi][ni], af[0][mi], bf[1][ni]);   // hi*lo
                    mma_bf16(acc[mi][ni], af[1][mi], bf[0][ni]);   // lo*hi
                }
        }
        __syncthreads();
    }

    // ---- epilogue ----
    const int er = (l >> 2);            // 0..7
    const int ec = (l & 3) * 2;         // 0,2,4,6
#pragma unroll
    for (int mi = 0; mi < 4; ++mi) {
#pragma unroll
        for (int half = 0; half < 2; ++half) {
            const int gm = bm0 + wr * 64 + mi * 16 + er + half * 8;
            if (gm >= M) continue;
#pragma unroll
            for (int ni = 0; ni < 4; ++ni) {
                const int gn = bn0 + wc * 32 + ni * 8 + ec;
                const float v0 = acc[mi][ni][half * 2 + 0] + __ldg(bias + gn);
                const float v1 = acc[mi][ni][half * 2 + 1] + __ldg(bias + gn + 1);
                if (EPI == 0) {
                    const float g0 = 0.5f * v0 * (1.0f + erff(v0 * 0.70710678118654752f));
                    const float g1 = 0.5f * v1 * (1.0f + erff(v1 * 0.70710678118654752f));
                    __nv_bfloat16 h0 = __float2bfloat16(g0);
                    __nv_bfloat16 h1 = __float2bfloat16(g1);
                    __nv_bfloat16 l0 = __float2bfloat16(g0 - __bfloat162float(h0));
                    __nv_bfloat16 l1 = __float2bfloat16(g1 - __bfloat162float(h1));
                    const size_t o = (size_t)gm * N + gn;
                    *reinterpret_cast<__nv_bfloat162*>((__nv_bfloat16*)Hh + o) =
                        __nv_bfloat162(h0, h1);
                    *reinterpret_cast<__nv_bfloat162*>((__nv_bfloat16*)Hl + o) =
                        __nv_bfloat162(l0, l1);
                } else {
                    float* dst = (gm < N_R)
                                     ? (outp + (size_t)gm * DFEAT + colOff + gn)
                                     : (outp + EP_OFF + (size_t)(gm - N_R) * DFEAT + colOff + gn);
                    dst[0] = 1.0f / (1.0f + expf(-v0));
                    dst[1] = 1.0f / (1.0f + expf(-v1));
                }
            }
        }
    }
}

// ---------------------------------------------------------------------------
// CNN head (unchanged)
// ---------------------------------------------------------------------------
#define SMX    0
#define SMW1   (SMX  + 2 * 516)
#define SMB1   (SMW1 + 240)
#define SMB2   (SMB1 + 16)
#define SMW2   (SMB2 + 32)
#define SMP1   (SMW2 + 7680)
#define SMRED  (SMP1 + 16 * 2 * 260)
#define SMTOT  (SMRED + 16)

__global__ __launch_bounds__(256)
void conv_head_k(const float* __restrict__ w1, const float* __restrict__ b1,
                 const float* __restrict__ w2, const float* __restrict__ b2,
                 const int* __restrict__ idx,
                 const float* __restrict__ Wout, const float* __restrict__ bout,
                 float* __restrict__ out)
{
    extern __shared__ float smf[];
    float* s_x  = smf + SMX;
    float* s_w1 = smf + SMW1;
    float* s_b1 = smf + SMB1;
    float* s_b2 = smf + SMB2;
    float* s_w2 = smf + SMW2;
    float* s_p1 = smf + SMP1;
    float* s_red = smf + SMRED;

    const int tid = threadIdx.x;
    const int b   = blockIdx.x;

    for (int i = tid; i < 2 * 516; i += 256) s_x[i] = 0.0f;
    for (int i = tid; i < 16 * 2 * 260; i += 256) s_p1[i] = 0.0f;
    for (int i = tid; i < 240; i += 256) s_w1[i] = w1[i];
    for (int i = tid; i < 7680; i += 256) s_w2[i] = w2[i];
    if (tid < 16) s_b1[tid] = b1[tid];
    if (tid >= 32 && tid < 64) s_b2[tid - 32] = b2[tid - 32];

    const int id   = idx[b];
    const int r_no = id / 1512;
    const int p_no = id - r_no * 1512;
    __syncthreads();

    for (int c = tid; c < DFEAT; c += 256) {
        s_x[2 + c]        = out[(size_t)r_no * DFEAT + c];
        s_x[516 + 2 + c]  = out[EP_OFF + (size_t)p_no * DFEAT + c];
    }
    __syncthreads();

    for (int j = tid; j < 16 * 2 * 256; j += 256) {
        const int oc = j >> 9;
        const int ph = (j >> 8) & 1;
        const int pw = j & 255;
        const float* w = s_w1 + oc * 15;
        const float bv = s_b1[oc];
        float sum = 0.0f;
#pragma unroll
        for (int dh = 0; dh < 2; ++dh) {
            const int oh = 2 * ph + dh;
#pragma unroll
            for (int dw = 0; dw < 2; ++dw) {
                const int ow = 2 * pw + dw;
                float c = 0.0f;
#pragma unroll
                for (int kh = 0; kh < 3; ++kh) {
                    const int ih = oh + kh - 2;
                    if (ih >= 0 && ih < 2) {
#pragma unroll
                        for (int kw = 0; kw < 5; ++kw)
                            c = fmaf(w[kh * 5 + kw], s_x[ih * 516 + ow + kw], c);
                    }
                }
                c += bv;
                sum += (c >= 0.0f) ? c : 0.01f * c;
            }
        }
        s_p1[(oc * 2 + ph) * 260 + 2 + pw] = 0.25f * sum;
    }
    __syncthreads();

    float ro0 = 0.0f, ro1 = 0.0f;
#pragma unroll
    for (int pass = 0; pass < 4; ++pass) {
        const int t   = tid + pass * 256;
        const int ocg = t >> 7;
        const int ph  = (t >> 6) & 1;
        const int pwg = t & 63;
        const int ow0 = pwg * 4;

        float accA[4][4], accB[4][4];
#pragma unroll
        for (int o = 0; o < 4; ++o)
#pragma unroll
            for (int j = 0; j < 4; ++j) { accA[o][j] = 0.0f; accB[o][j] = 0.0f; }

        const int khA0 = 2 - 2 * ph;
#pragma unroll
        for (int ic = 0; ic < 16; ++ic) {
#pragma unroll
            for (int ih = 0; ih < 2; ++ih) {
                const float* rowp = s_p1 + (ic * 2 + ih) * 260;
                float4 u0 = *reinterpret_cast<const float4*>(rowp + ow0);
                float4 u1 = *reinterpret_cast<const float4*>(rowp + ow0 + 4);
                float in[8] = {u0.x, u0.y, u0.z, u0.w, u1.x, u1.y, u1.z, u1.w};

                const int khA = ih + khA0;
                if (khA >= 0 && khA < 3) {
#pragma unroll
                    for (int o = 0; o < 4; ++o) {
                        const float* w = s_w2 + ((((ocg * 4 + o) * 16 + ic) * 3 + khA) * 5);
#pragma unroll
                        for (int kw = 0; kw < 5; ++kw) {
                            const float wv = w[kw];
#pragma unroll
                            for (int j = 0; j < 4; ++j)
                                accA[o][j] = fmaf(wv, in[j + kw], accA[o][j]);
                        }
                    }
                }
                const int khB = khA - 1;
                if (khB >= 0 && khB < 3) {
#pragma unroll
                    for (int o = 0; o < 4; ++o) {
                        const float* w = s_w2 + ((((ocg * 4 + o) * 16 + ic) * 3 + khB) * 5);
#pragma unroll
                        for (int kw = 0; kw < 5; ++kw) {
                            const float wv = w[kw];
#pragma unroll
                            for (int j = 0; j < 4; ++j)
                                accB[o][j] = fmaf(wv, in[j + kw], accB[o][j]);
                        }
                    }
                }
            }
        }
#pragma unroll
        for (int o = 0; o < 4; ++o) {
            const int oc = ocg * 4 + o;
            const float bv = s_b2[oc];
#pragma unroll
            for (int p = 0; p < 2; ++p) {
                float m = fmaxf(fmaxf(accA[o][2 * p], accA[o][2 * p + 1]),
                                fmaxf(accB[o][2 * p], accB[o][2 * p + 1]));
                float v = m + bv;
                v = (v >= 0.0f) ? v : 0.01f * v;
                float tv = tanhf(v);
                const int f = oc * 256 + ph * 128 + (pwg * 2 + p);
                out[FLAT_OFF + (size_t)b * 8192 + f] = tv;
                ro0 = fmaf(tv, Wout[2 * f], ro0);
                ro1 = fmaf(tv, Wout[2 * f + 1], ro1);
            }
        }
    }

#pragma unroll
    for (int off = 16; off > 0; off >>= 1) {
        ro0 += __shfl_down_sync(0xffffffffu, ro0, off);
        ro1 += __shfl_down_sync(0xffffffffu, ro1, off);
    }
    const int warp = tid >> 5, lane = tid & 31;
    if (lane == 0) { s_red[warp] = ro0; s_red[8 + warp] = ro1; }
    __syncthreads();
    if (tid == 0) {
        float a = 0.0f, c = 0.0f;
#pragma unroll
        for (int i = 0; i < 8; ++i) { a += s_red[i]; c += s_red[8 + i]; }
        out[OUT2_OFF + (size_t)b * 2 + 0] = a + bout[0];
        out[OUT2_OFF + (size_t)b * 2 + 1] = c + bout[1];
    }
}

// ---------------------------------------------------------------------------
extern "C" void kernel_launch(void* const* d_in, const int* in_sizes, int n_in,
                              void* d_out, int out_size)
{
    const float* r_att   = (const float*)d_in[0];
    const float* p_att   = (const float*)d_in[1];
    const float* r_fun   = (const float*)d_in[2];
    const float* p_fun   = (const float*)d_in[3];
    const int*   idx     = (const int*)  d_in[4];
    const float* W_att1  = (const float*)d_in[5];
    const float* b_att1  = (const float*)d_in[6];
    const float* W_att2  = (const float*)d_in[7];
    const float* b_att2  = (const float*)d_in[8];
    const float* W_fun1  = (const float*)d_in[9];
    const float* b_fun1  = (const float*)d_in[10];
    const float* W_fun2  = (const float*)d_in[11];
    const float* b_fun2  = (const float*)d_in[12];
    const float* conv1_w = (const float*)d_in[13];
    const float* conv1_b = (const float*)d_in[14];
    const float* conv2_w = (const float*)d_in[15];
    const float* conv2_b = (const float*)d_in[16];
    const float* W_out   = (const float*)d_in[17];
    const float* b_out   = (const float*)d_in[18];
    float* out = (float*)d_out;

    unsigned short *pAh, *pAl, *pBh, *pBl, *pHh, *pHl;
    cudaGetSymbolAddress((void**)&pAh, gAh);
    cudaGetSymbolAddress((void**)&pAl, gAl);
    cudaGetSymbolAddress((void**)&pBh, gBh);
    cudaGetSymbolAddress((void**)&pBl, gBl);
    cudaGetSymbolAddress((void**)&pHh, gHh);
    cudaGetSymbolAddress((void**)&pHl, gHl);

    cudaFuncSetAttribute(hmma_gemm<0>, cudaFuncAttributeMaxDynamicSharedMemorySize, HS_SMEM);
    cudaFuncSetAttribute(hmma_gemm<1>, cudaFuncAttributeMaxDynamicSharedMemorySize, HS_SMEM);
    const size_t conv_smem = SMTOT * sizeof(float);
    cudaFuncSetAttribute(conv_head_k, cudaFuncAttributeMaxDynamicSharedMemorySize, (int)conv_smem);

    dim3 t328(32, 8);

    // ---- ATT branch ----
    convA_split<<<dim3((KP_ATT + 255) / 256, M_TOT), 256>>>(r_att, p_att, N_R, SIZE_R, KP_ATT, pAh, pAl);
    convT_split<<<dim3(ATT_H / 32, KP_ATT / 32), t328>>>(W_att1, SIZE_R, ATT_H, KP_ATT, pBh, pBl);
    hmma_gemm<0><<<dim3(ATT_H / 128, 28), 256, HS_SMEM>>>(
        pAh, pAl, M_TOT, KP_ATT, pBh, pBl, ATT_H, b_att1, nullptr, pHh, pHl, 0);
    convT_split<<<dim3(256 / 32, ATT_H / 32), t328>>>(W_att2, ATT_H, 256, ATT_H, pBh, pBl);
    hmma_gemm<1><<<dim3(256 / 128, 28), 256, HS_SMEM>>>(
        pHh, pHl, M_TOT, ATT_H, pBh, pBl, 256, b_att2, out, nullptr, nullptr, 0);

    // ---- FUN branch ----
    convA_split<<<dim3((KP_FUN + 255) / 256, M_TOT), 256>>>(r_fun, p_fun, N_R, FUN_IN, KP_FUN, pAh, pAl);
    convT_split<<<dim3(FUN_H / 32, KP_FUN / 32), t328>>>(W_fun1, FUN_IN, FUN_H, KP_FUN, pBh, pBl);
    hmma_gemm<0><<<dim3(FUN_H / 128, 28), 256, HS_SMEM>>>(
        pAh, pAl, M_TOT, KP_FUN, pBh, pBl, FUN_H, b_fun1, nullptr, pHh, pHl, 0);
    convT_split<<<dim3(256 / 32, FUN_H / 32), t328>>>(W_fun2, FUN_H, 256, FUN_H, pBh, pBl);
    hmma_gemm<1><<<dim3(256 / 128, 28), 256, HS_SMEM>>>(
        pHh, pHl, M_TOT, FUN_H, pBh, pBl, 256, b_fun2, out, nullptr, nullptr, 256);

    // ---- CNN head ----
    conv_head_k<<<BATCH, 256, conv_smem>>>(
        conv1_w, conv1_b, conv2_w, conv2_b, idx, W_out, b_out, out);

    (void)in_sizes; (void)n_in; (void)out_size;
}